// round 2
// baseline (speedup 1.0000x reference)
#include <cuda_runtime.h>
#include <math.h>
#include <cstdint>

// Problem constants
#define DD    768
#define BINS  385
#define CPF   770          // floats per transform = 2*BINS
#define NCOLS 2310         // 3*CPF (k|v|q spectra concatenated)
#define NTOK  16384        // B*S
#define SEQ   4096
#define BATCH 4
#define KPAD  784          // padded outF row length (multiple of 16)

// Scratch (device globals; allocation-free per harness rules)
__device__ float g_E[DD * CPF];        // forward rDFT matrix [e][j]
__device__ float g_M[DD * NCOLS];      // combined Wk^T*E | Wv^T*E | Wq^T*E
__device__ float g_F[NTOK * NCOLS];    // kf|vf|qf per token
__device__ float g_OutF[NTOK * KPAD];  // mem * conj(qf), K-padded
__device__ float g_G[KPAD * DD];       // inverse rDFT matrix [j][n]

// ---------------------------------------------------------------------------
// Fill kernels
// ---------------------------------------------------------------------------
__global__ void fill_E() {
    int idx = blockIdx.x * blockDim.x + threadIdx.x;
    if (idx >= DD * CPF) return;
    int e = idx / CPF, j = idx % CPF;
    int m = j >> 1;
    int r = (e * m) % DD;
    float th = (float)r * (float)(2.0 * M_PI / DD);
    float s, c;
    sincosf(th, &s, &c);
    g_E[idx] = (j & 1) ? -s : c;   // exp(-i*2pi*e*m/D): (cos, -sin)
}

__global__ void fill_G() {
    int idx = blockIdx.x * blockDim.x + threadIdx.x;
    if (idx >= KPAD * DD) return;
    int j = idx / DD, n = idx % DD;
    float v = 0.f;
    if (j < CPF) {
        int m = j >> 1;
        float w = (m == 0 || m == BINS - 1) ? 1.f : 2.f;
        int r = (m * n) % DD;
        float th = (float)r * (float)(2.0 * M_PI / DD);
        float s, c;
        sincosf(th, &s, &c);
        v = ((j & 1) ? -s : c) * (w / (float)DD);
    }
    g_G[idx] = v;
}

__global__ void zero_pad_outf() {
    int idx = blockIdx.x * blockDim.x + threadIdx.x;
    const int PADC = KPAD - CPF; // 14
    if (idx >= NTOK * PADC) return;
    int t = idx / PADC, c = CPF + idx % PADC;
    g_OutF[(size_t)t * KPAD + c] = 0.f;
}

// ---------------------------------------------------------------------------
// SGEMM: C[M,N] = A(^T) * B ; optional epilogue C = X + gain*acc
//   TRANSA=0: A is MxK row-major;  TRANSA=1: A is KxM row-major (i.e. C=A^T B)
//   gridDim.z selects A0/A1/A2 with column offset z*zcolstride in C.
// ---------------------------------------------------------------------------
#define BM 128
#define BN 128
#define BKK 16
#define TM 8
#define TNW 8

template <int TRANSA>
__global__ __launch_bounds__(256) void sgemm(
    int M, int N, int K,
    const float* __restrict__ A0, const float* __restrict__ A1,
    const float* __restrict__ A2, int lda,
    const float* __restrict__ Bm, int ldb,
    float* __restrict__ C, int ldc, int zcolstride,
    int epi, const float* __restrict__ X, const float* __restrict__ gainp)
{
    __shared__ float As[BKK][BM];
    __shared__ float Bs[BKK][BN];

    const float* A = (blockIdx.z == 0) ? A0 : ((blockIdx.z == 1) ? A1 : A2);
    const int coff = blockIdx.z * zcolstride;

    const int tid = threadIdx.x;
    const int bm0 = blockIdx.y * BM;
    const int bn0 = blockIdx.x * BN;
    const int tr = (tid >> 4) * TM;
    const int tc = (tid & 15) * TNW;

    float acc[TM][TNW];
#pragma unroll
    for (int i = 0; i < TM; i++)
#pragma unroll
        for (int j = 0; j < TNW; j++) acc[i][j] = 0.f;

    for (int k0 = 0; k0 < K; k0 += BKK) {
        if (TRANSA == 0) {
            int aRow = tid >> 2;
            int aCol = (tid & 3) << 2;
#pragma unroll
            for (int r = 0; r < 2; r++) {
                int row = aRow + r * 64;
                float4 v = *reinterpret_cast<const float4*>(
                    A + (size_t)(bm0 + row) * lda + (k0 + aCol));
                As[aCol + 0][row] = v.x;
                As[aCol + 1][row] = v.y;
                As[aCol + 2][row] = v.z;
                As[aCol + 3][row] = v.w;
            }
        } else {
            int aRow = tid >> 5;          // k-row within tile (0..7)
            int aCol = (tid & 31) << 2;   // m-col (0..124)
#pragma unroll
            for (int r = 0; r < 2; r++) {
                int row = aRow + r * 8;
                float4 v = *reinterpret_cast<const float4*>(
                    A + (size_t)(k0 + row) * lda + (bm0 + aCol));
                *reinterpret_cast<float4*>(&As[row][aCol]) = v;
            }
        }
        // B tile: scalar guarded loads (N may be non-multiple of 128 / unaligned)
#pragma unroll
        for (int i = 0; i < 8; i++) {
            int flat = tid + i * 256;
            int row = flat >> 7;
            int col = flat & 127;
            int gcol = bn0 + col;
            Bs[row][col] = (gcol < N) ? Bm[(size_t)(k0 + row) * ldb + gcol] : 0.f;
        }
        __syncthreads();
#pragma unroll
        for (int kk = 0; kk < BKK; kk++) {
            float a[TM], b[TNW];
#pragma unroll
            for (int i = 0; i < TM; i++) a[i] = As[kk][tr + i];
#pragma unroll
            for (int j = 0; j < TNW; j++) b[j] = Bs[kk][tc + j];
#pragma unroll
            for (int i = 0; i < TM; i++)
#pragma unroll
                for (int j = 0; j < TNW; j++) acc[i][j] += a[i] * b[j];
        }
        __syncthreads();
    }

    float g = epi ? gainp[0] : 0.f;
#pragma unroll
    for (int i = 0; i < TM; i++) {
        int gm = bm0 + tr + i;
#pragma unroll
        for (int j = 0; j < TNW; j++) {
            int gn = bn0 + tc + j;
            if (gn < N) {
                float v = acc[i][j];
                size_t cidx = (size_t)gm * ldc + coff + gn;
                if (epi) v = X[cidx] + g * v;
                C[cidx] = v;
            }
        }
    }
}

// ---------------------------------------------------------------------------
// Causal complex cumsum of kf*vf per (batch, bin), times conj(qf).
// Block = (8 bins, 32 seq-lanes); each lane owns 128 consecutive s.
// Two passes over g_F: local sums -> smem exclusive scan -> replay & emit.
// ---------------------------------------------------------------------------
__global__ void scan_kernel() {
    int b = blockIdx.x;
    int mg = blockIdx.y;
    int j = threadIdx.x;   // bin within group (0..7)
    int l = threadIdx.y;   // seq chunk lane (0..31)
    int m = mg * 8 + j;
    bool act = (m < BINS);
    const int CH = SEQ / 32;   // 128
    int sbase = b * SEQ + l * CH;
    int km = 2 * m;

    float sre = 0.f, sim = 0.f;
    if (act) {
        const float* base = g_F + (size_t)sbase * NCOLS;
        for (int i = 0; i < CH; i++) {
            const float* row = base + (size_t)i * NCOLS;
            float2 kf = *reinterpret_cast<const float2*>(row + km);
            float2 vf = *reinterpret_cast<const float2*>(row + CPF + km);
            sre += kf.x * vf.x - kf.y * vf.y;
            sim += kf.x * vf.y + kf.y * vf.x;
        }
    }
    __shared__ float pr[8][33], pi[8][33];
    pr[j][l] = sre;
    pi[j][l] = sim;
    __syncthreads();
    if (l == 0) {  // exclusive scan over the 32 lane partials, per bin
        float ar = 0.f, ai = 0.f;
        for (int q = 0; q < 32; q++) {
            float tr_ = pr[j][q], ti = pi[j][q];
            pr[j][q] = ar;
            pi[j][q] = ai;
            ar += tr_;
            ai += ti;
        }
    }
    __syncthreads();
    if (act) {
        float ar = pr[j][l], ai = pi[j][l];
        for (int i = 0; i < CH; i++) {
            int t = sbase + i;
            const float* row = g_F + (size_t)t * NCOLS;
            float2 kf = *reinterpret_cast<const float2*>(row + km);
            float2 vf = *reinterpret_cast<const float2*>(row + CPF + km);
            float2 qf = *reinterpret_cast<const float2*>(row + 2 * CPF + km);
            ar += kf.x * vf.x - kf.y * vf.y;          // mem (inclusive cumsum)
            ai += kf.x * vf.y + kf.y * vf.x;
            float outr = ar * qf.x + ai * qf.y;       // mem * conj(qf)
            float outi = ai * qf.x - ar * qf.y;
            *reinterpret_cast<float2*>(g_OutF + (size_t)t * KPAD + km) =
                make_float2(outr, outi);
        }
    }
}

// ---------------------------------------------------------------------------
// Launch
// ---------------------------------------------------------------------------
extern "C" void kernel_launch(void* const* d_in, const int* in_sizes, int n_in,
                              void* d_out, int out_size) {
    const float* x    = (const float*)d_in[0];
    const float* Wk   = (const float*)d_in[1];
    const float* Wv   = (const float*)d_in[2];
    const float* Wq   = (const float*)d_in[3];
    const float* gain = (const float*)d_in[4];
    float* out = (float*)d_out;

    float *pE, *pM, *pF, *pO, *pG;
    cudaGetSymbolAddress((void**)&pE, g_E);
    cudaGetSymbolAddress((void**)&pM, g_M);
    cudaGetSymbolAddress((void**)&pF, g_F);
    cudaGetSymbolAddress((void**)&pO, g_OutF);
    cudaGetSymbolAddress((void**)&pG, g_G);

    fill_E<<<(DD * CPF + 255) / 256, 256>>>();
    fill_G<<<(KPAD * DD + 255) / 256, 256>>>();
    zero_pad_outf<<<(NTOK * (KPAD - CPF) + 255) / 256, 256>>>();

    // Precompute combined matrices: M_p = W_p^T @ E  (C = A^T B), 3 projections via z
    {
        dim3 grid((CPF + BN - 1) / BN, (DD + BM - 1) / BM, 3);
        sgemm<1><<<grid, 256>>>(DD, CPF, DD, Wk, Wv, Wq, DD,
                                pE, CPF, pM, NCOLS, CPF, 0, nullptr, nullptr);
    }
    // Forward: F = x @ M  -> kf|vf|qf spectra
    {
        dim3 grid((NCOLS + BN - 1) / BN, NTOK / BM, 1);
        sgemm<0><<<grid, 256>>>(NTOK, NCOLS, DD, x, x, x, DD,
                                pM, NCOLS, pF, NCOLS, 0, 0, nullptr, nullptr);
    }
    // Causal binding scan
    {
        dim3 grid(BATCH, (BINS + 7) / 8, 1);
        scan_kernel<<<grid, dim3(8, 32, 1)>>>();
    }
    // Inverse: out = x + gain * (OutF @ G)
    {
        dim3 grid(DD / BN, NTOK / BM, 1);
        sgemm<0><<<grid, 256>>>(NTOK, DD, KPAD, pO, pO, pO, KPAD,
                                pG, DD, out, DD, 0, 1, x, gain);
    }
}

// round 3
// speedup vs baseline: 3.5056x; 3.5056x over previous
#include <cuda_runtime.h>
#include <math.h>
#include <cstdint>

// Problem constants
#define DD     768
#define BINS   385
#define CPF    770          // floats per transform = 2*BINS
#define NVALID 2310         // 3*CPF valid F columns
#define NCF    2432         // padded F width (19*128)
#define NTOK   16384        // B*S
#define SEQ    4096
#define BATCH  4
#define KPAD   800          // padded OutF row length (25*32)

// Scratch (device globals; allocation-free per harness rules)
__device__ float g_E[DD * CPF];              // forward rDFT matrix [e][j]
__device__ float g_M[DD * NCF];              // combined Wk^T*E | Wv^T*E | Wq^T*E (padded)
__device__ float g_Mp[4][DD * NCF];          // K-split partials (deterministic reduce)
__device__ float g_F[(size_t)NTOK * NCF];    // kf|vf|qf per token (padded)
__device__ float g_OutF[(size_t)NTOK * KPAD];// mem * conj(qf), K-padded
__device__ float g_G[KPAD * DD];             // inverse rDFT matrix [j][n]

// ---------------------------------------------------------------------------
// Fill kernels
// ---------------------------------------------------------------------------
__global__ void fill_E() {
    int idx = blockIdx.x * blockDim.x + threadIdx.x;
    if (idx >= DD * CPF) return;
    int e = idx / CPF, j = idx % CPF;
    int m = j >> 1;
    int r = (e * m) % DD;
    float th = (float)r * (float)(2.0 * M_PI / DD);
    float s, c;
    sincosf(th, &s, &c);
    g_E[idx] = (j & 1) ? -s : c;   // exp(-i*2pi*e*m/D): (cos, -sin)
}

__global__ void fill_G() {
    int idx = blockIdx.x * blockDim.x + threadIdx.x;
    if (idx >= KPAD * DD) return;
    int j = idx / DD, n = idx % DD;
    float v = 0.f;
    if (j < CPF) {
        int m = j >> 1;
        float w = (m == 0 || m == BINS - 1) ? 1.f : 2.f;
        int r = (m * n) % DD;
        float th = (float)r * (float)(2.0 * M_PI / DD);
        float s, c;
        sincosf(th, &s, &c);
        v = ((j & 1) ? -s : c) * (w / (float)DD);
    }
    g_G[idx] = v;
}

__global__ void zero_pad_outf() {
    int idx = blockIdx.x * blockDim.x + threadIdx.x;
    const int PADC = KPAD - CPF; // 30
    if (idx >= NTOK * PADC) return;
    int t = idx / PADC, c = CPF + idx % PADC;
    g_OutF[(size_t)t * KPAD + c] = 0.f;
}

// ---------------------------------------------------------------------------
// Precompute: M_p = W_p^T @ E, fp32, K split by 4 into partial buffers
// grid = (ceil(770/128), 6, 12)  z = proj*4 + slice
// ---------------------------------------------------------------------------
#define PBM 128
#define PBN 128
#define PBK 16

__global__ __launch_bounds__(256) void precompute_gemm(
    const float* __restrict__ Wk, const float* __restrict__ Wv,
    const float* __restrict__ Wq)
{
    const int M = DD, N = CPF, K = DD, lda = DD, ldb = CPF;
    __shared__ float As[PBK][PBM];
    __shared__ float Bs[PBK][PBN];

    int z = blockIdx.z;
    int proj = z >> 2, slice = z & 3;
    const float* A = (proj == 0) ? Wk : ((proj == 1) ? Wv : Wq);
    float* Cc = g_Mp[slice];
    const int coff = proj * CPF;
    const int kbeg = slice * (K / 4);   // 192 per slice
    const int kend = kbeg + K / 4;

    const int tid = threadIdx.x;
    const int bm0 = blockIdx.y * PBM;
    const int bn0 = blockIdx.x * PBN;
    const int tr = (tid >> 4) * 8;
    const int tc = (tid & 15) * 8;

    float acc[8][8];
#pragma unroll
    for (int i = 0; i < 8; i++)
#pragma unroll
        for (int j = 0; j < 8; j++) acc[i][j] = 0.f;

    for (int k0 = kbeg; k0 < kend; k0 += PBK) {
        // A is KxM row-major (C = A^T B)
        int aRow = tid >> 5;
        int aCol = (tid & 31) << 2;
#pragma unroll
        for (int r = 0; r < 2; r++) {
            int row = aRow + r * 8;
            float4 v = *reinterpret_cast<const float4*>(
                A + (size_t)(k0 + row) * lda + (bm0 + aCol));
            *reinterpret_cast<float4*>(&As[row][aCol]) = v;
        }
#pragma unroll
        for (int i = 0; i < 8; i++) {
            int flat = tid + i * 256;
            int row = flat >> 7;
            int col = flat & 127;
            int gcol = bn0 + col;
            Bs[row][col] = (gcol < N) ? g_E[(size_t)(k0 + row) * ldb + gcol] : 0.f;
        }
        __syncthreads();
#pragma unroll
        for (int kk = 0; kk < PBK; kk++) {
            float a[8], b[8];
#pragma unroll
            for (int i = 0; i < 8; i++) a[i] = As[kk][tr + i];
#pragma unroll
            for (int j = 0; j < 8; j++) b[j] = Bs[kk][tc + j];
#pragma unroll
            for (int i = 0; i < 8; i++)
#pragma unroll
                for (int j = 0; j < 8; j++) acc[i][j] += a[i] * b[j];
        }
        __syncthreads();
    }

#pragma unroll
    for (int i = 0; i < 8; i++) {
        int gm = bm0 + tr + i;
        if (gm >= M) continue;
#pragma unroll
        for (int j = 0; j < 8; j++) {
            int gn = bn0 + tc + j;
            if (gn < N) Cc[(size_t)gm * NCF + coff + gn] = acc[i][j];
        }
    }
}

__global__ void reduce_M() {
    int i = blockIdx.x * blockDim.x + threadIdx.x;
    if (i >= DD * NCF) return;
    int col = i % NCF;
    float v = 0.f;
    if (col < NVALID)
        v = g_Mp[0][i] + g_Mp[1][i] + g_Mp[2][i] + g_Mp[3][i];
    g_M[i] = v;
}

// ---------------------------------------------------------------------------
// TF32 tensor-core GEMM: C[M,N] = A[M,K] * B[K,N]   (all row-major)
// Requires M%128==0, N%128==0, K%32==0 (we pad buffers so this holds).
// Optional epilogue: C = X + gain*acc.
// 256 threads, warp tile 64x32 (2x4 warp grid), m16n8k8 tf32 mma.
// ---------------------------------------------------------------------------
#define GBM 128
#define GBN 128
#define GBK 32
#define APAD 36                 // smem A row stride (floats) -> conflict-free ldmatrix
#define BPAD 136                // smem B row stride (floats) -> conflict-free lds
#define A_ST (GBM * APAD)       // 4608 floats per stage
#define B_ST (GBK * BPAD)       // 4352 floats per stage
#define GSMEM_BYTES ((2 * A_ST + 2 * B_ST) * 4)   // 71680 B

__device__ __forceinline__ float cvt_tf32(float x) {
    uint32_t u;
    asm("cvt.rna.tf32.f32 %0, %1;" : "=r"(u) : "f"(x));
    return __uint_as_float(u);
}
__device__ __forceinline__ float4 cvt4(float4 v) {
    float4 o;
    o.x = cvt_tf32(v.x); o.y = cvt_tf32(v.y);
    o.z = cvt_tf32(v.z); o.w = cvt_tf32(v.w);
    return o;
}
__device__ __forceinline__ void ldsm4(uint32_t* r, uint32_t addr) {
    asm volatile("ldmatrix.sync.aligned.m8n8.x4.shared.b16 {%0,%1,%2,%3}, [%4];\n"
        : "=r"(r[0]), "=r"(r[1]), "=r"(r[2]), "=r"(r[3]) : "r"(addr));
}
__device__ __forceinline__ void mma_tf32(float* d, const uint32_t* a, const uint32_t* b) {
    asm volatile(
        "mma.sync.aligned.m16n8k8.row.col.f32.tf32.tf32.f32 "
        "{%0,%1,%2,%3}, {%4,%5,%6,%7}, {%8,%9}, {%0,%1,%2,%3};\n"
        : "+f"(d[0]), "+f"(d[1]), "+f"(d[2]), "+f"(d[3])
        : "r"(a[0]), "r"(a[1]), "r"(a[2]), "r"(a[3]), "r"(b[0]), "r"(b[1]));
}

__global__ __launch_bounds__(256) void gemm_tf32(
    int M, int N, int K,
    const float* __restrict__ A, int lda,
    const float* __restrict__ B, int ldb,
    float* __restrict__ C, int ldc,
    int epi, const float* __restrict__ X, const float* __restrict__ gainp)
{
    extern __shared__ float sm[];
    float* smA = sm;              // [2][GBM][APAD]
    float* smB = sm + 2 * A_ST;   // [2][GBK][BPAD]

    const int tid  = threadIdx.x;
    const int lane = tid & 31;
    const int wid  = tid >> 5;
    const int wm   = (wid >> 2) * 64;   // warp m offset (0 or 64)
    const int wn   = (wid & 3) * 32;    // warp n offset (0..96)
    const int bm0  = blockIdx.y * GBM;
    const int bn0  = blockIdx.x * GBN;

    // gmem staging mapping
    const int arow = tid >> 3;          // 0..31
    const int acol = (tid & 7) * 4;     // 0..28
    const int brow = tid >> 5;          // 0..7
    const int bcol = (tid & 31) * 4;    // 0..124

    const float* Aptr = A + (size_t)(bm0 + arow) * lda + acol;
    const float* Bptr = B + (size_t)brow * ldb + bn0 + bcol;

    // A fragment ldmatrix address offset (floats, within a stage)
    const int rin = lane & 7;
    const int sel = lane >> 3;
    const int aoff = (wm + (sel & 1) * 8 + rin) * APAD + (sel >> 1) * 4;
    const uint32_t smA_u = (uint32_t)__cvta_generic_to_shared(smA);
    // B fragment scalar-lds offsets
    const int bk_f = lane & 3;          // k within 4
    const int bn_f = wn + (lane >> 2);  // n base

    float4 rA[4], rB[4];
    // prologue: tile 0
#pragma unroll
    for (int r = 0; r < 4; r++)
        rA[r] = *reinterpret_cast<const float4*>(Aptr + (size_t)(r * 32) * lda);
#pragma unroll
    for (int r = 0; r < 4; r++)
        rB[r] = *reinterpret_cast<const float4*>(Bptr + (size_t)(r * 8) * ldb);
#pragma unroll
    for (int r = 0; r < 4; r++)
        *reinterpret_cast<float4*>(&smA[(arow + r * 32) * APAD + acol]) = cvt4(rA[r]);
#pragma unroll
    for (int r = 0; r < 4; r++)
        *reinterpret_cast<float4*>(&smB[(brow + r * 8) * BPAD + bcol]) = cvt4(rB[r]);
    __syncthreads();

    float acc[4][4][4];
#pragma unroll
    for (int mf = 0; mf < 4; mf++)
#pragma unroll
        for (int nf = 0; nf < 4; nf++)
#pragma unroll
            for (int q = 0; q < 4; q++) acc[mf][nf][q] = 0.f;

    const int KT = K / GBK;
    int st = 0;
    for (int kt = 0; kt < KT; kt++) {
        if (kt + 1 < KT) {
            size_t k0n = (size_t)(kt + 1) * GBK;
#pragma unroll
            for (int r = 0; r < 4; r++)
                rA[r] = *reinterpret_cast<const float4*>(Aptr + (size_t)(r * 32) * lda + k0n);
#pragma unroll
            for (int r = 0; r < 4; r++)
                rB[r] = *reinterpret_cast<const float4*>(Bptr + (k0n + r * 8) * ldb);
        }
        // compute current stage
        {
            const uint32_t aBase = smA_u + (uint32_t)(st * A_ST) * 4;
            const float* pb = smB + st * B_ST;
#pragma unroll
            for (int ks = 0; ks < 4; ks++) {
                uint32_t a[4][4];
#pragma unroll
                for (int mf = 0; mf < 4; mf++)
                    ldsm4(a[mf], aBase + (uint32_t)(aoff + mf * 16 * APAD + ks * 8) * 4);
                uint32_t b[4][2];
#pragma unroll
                for (int nf = 0; nf < 4; nf++) {
                    b[nf][0] = __float_as_uint(pb[(ks * 8 + bk_f) * BPAD + bn_f + nf * 8]);
                    b[nf][1] = __float_as_uint(pb[(ks * 8 + bk_f + 4) * BPAD + bn_f + nf * 8]);
                }
#pragma unroll
                for (int mf = 0; mf < 4; mf++)
#pragma unroll
                    for (int nf = 0; nf < 4; nf++)
                        mma_tf32(acc[mf][nf], a[mf], b[nf]);
            }
        }
        if (kt + 1 < KT) {
            int ns = st ^ 1;
            float* dA = smA + ns * A_ST;
            float* dB = smB + ns * B_ST;
#pragma unroll
            for (int r = 0; r < 4; r++)
                *reinterpret_cast<float4*>(&dA[(arow + r * 32) * APAD + acol]) = cvt4(rA[r]);
#pragma unroll
            for (int r = 0; r < 4; r++)
                *reinterpret_cast<float4*>(&dB[(brow + r * 8) * BPAD + bcol]) = cvt4(rB[r]);
        }
        __syncthreads();
        st ^= 1;
    }

    // epilogue
    float g = epi ? gainp[0] : 0.f;
#pragma unroll
    for (int mf = 0; mf < 4; mf++) {
        int row = bm0 + wm + mf * 16 + (lane >> 2);
#pragma unroll
        for (int nf = 0; nf < 4; nf++) {
            int col = bn0 + wn + nf * 8 + (lane & 3) * 2;
            size_t i0 = (size_t)row * ldc + col;
            size_t i1 = i0 + (size_t)8 * ldc;
            float2 v0 = make_float2(acc[mf][nf][0], acc[mf][nf][1]);
            float2 v1 = make_float2(acc[mf][nf][2], acc[mf][nf][3]);
            if (epi) {
                float2 x0 = *reinterpret_cast<const float2*>(X + i0);
                float2 x1 = *reinterpret_cast<const float2*>(X + i1);
                v0.x = x0.x + g * v0.x; v0.y = x0.y + g * v0.y;
                v1.x = x1.x + g * v1.x; v1.y = x1.y + g * v1.y;
            }
            *reinterpret_cast<float2*>(C + i0) = v0;
            *reinterpret_cast<float2*>(C + i1) = v1;
        }
    }
}

// ---------------------------------------------------------------------------
// Causal complex cumsum of kf*vf per (batch, bin), times conj(qf). fp32.
// ---------------------------------------------------------------------------
__global__ void scan_kernel() {
    int b = blockIdx.x;
    int mg = blockIdx.y;
    int j = threadIdx.x;   // bin within group (0..7)
    int l = threadIdx.y;   // seq chunk lane (0..31)
    int m = mg * 8 + j;
    bool act = (m < BINS);
    const int CH = SEQ / 32;   // 128
    int sbase = b * SEQ + l * CH;
    int km = 2 * m;

    float sre = 0.f, sim = 0.f;
    if (act) {
        const float* base = g_F + (size_t)sbase * NCF;
        for (int i = 0; i < CH; i++) {
            const float* row = base + (size_t)i * NCF;
            float2 kf = *reinterpret_cast<const float2*>(row + km);
            float2 vf = *reinterpret_cast<const float2*>(row + CPF + km);
            sre += kf.x * vf.x - kf.y * vf.y;
            sim += kf.x * vf.y + kf.y * vf.x;
        }
    }
    __shared__ float pr[8][33], pi[8][33];
    pr[j][l] = sre;
    pi[j][l] = sim;
    __syncthreads();
    if (l == 0) {
        float ar = 0.f, ai = 0.f;
        for (int q = 0; q < 32; q++) {
            float tr_ = pr[j][q], ti = pi[j][q];
            pr[j][q] = ar;
            pi[j][q] = ai;
            ar += tr_;
            ai += ti;
        }
    }
    __syncthreads();
    if (act) {
        float ar = pr[j][l], ai = pi[j][l];
        for (int i = 0; i < CH; i++) {
            int t = sbase + i;
            const float* row = g_F + (size_t)t * NCF;
            float2 kf = *reinterpret_cast<const float2*>(row + km);
            float2 vf = *reinterpret_cast<const float2*>(row + CPF + km);
            float2 qf = *reinterpret_cast<const float2*>(row + 2 * CPF + km);
            ar += kf.x * vf.x - kf.y * vf.y;
            ai += kf.x * vf.y + kf.y * vf.x;
            float outr = ar * qf.x + ai * qf.y;
            float outi = ai * qf.x - ar * qf.y;
            *reinterpret_cast<float2*>(g_OutF + (size_t)t * KPAD + km) =
                make_float2(outr, outi);
        }
    }
}

// ---------------------------------------------------------------------------
// Launch
// ---------------------------------------------------------------------------
extern "C" void kernel_launch(void* const* d_in, const int* in_sizes, int n_in,
                              void* d_out, int out_size) {
    const float* x    = (const float*)d_in[0];
    const float* Wk   = (const float*)d_in[1];
    const float* Wv   = (const float*)d_in[2];
    const float* Wq   = (const float*)d_in[3];
    const float* gain = (const float*)d_in[4];
    float* out = (float*)d_out;

    float *pM, *pF, *pO, *pG;
    cudaGetSymbolAddress((void**)&pM, g_M);
    cudaGetSymbolAddress((void**)&pF, g_F);
    cudaGetSymbolAddress((void**)&pO, g_OutF);
    cudaGetSymbolAddress((void**)&pG, g_G);

    cudaFuncSetAttribute(gemm_tf32, cudaFuncAttributeMaxDynamicSharedMemorySize,
                         GSMEM_BYTES);

    fill_E<<<(DD * CPF + 255) / 256, 256>>>();
    fill_G<<<(KPAD * DD + 255) / 256, 256>>>();
    zero_pad_outf<<<(NTOK * (KPAD - CPF) + 255) / 256, 256>>>();

    // Precompute M = W^T E (fp32, K split x4, deterministic reduce)
    {
        dim3 grid((CPF + PBN - 1) / PBN, (DD + PBM - 1) / PBM, 12);
        precompute_gemm<<<grid, 256>>>(Wk, Wv, Wq);
        reduce_M<<<(DD * NCF + 255) / 256, 256>>>();
    }
    // Forward: F = x @ M  (tf32 tensor cores, padded N)
    {
        dim3 grid(NCF / GBN, NTOK / GBM, 1);
        gemm_tf32<<<grid, 256, GSMEM_BYTES>>>(NTOK, NCF, DD, x, DD,
                                              pM, NCF, pF, NCF,
                                              0, nullptr, nullptr);
    }
    // Causal binding scan
    {
        dim3 grid(BATCH, (BINS + 7) / 8, 1);
        scan_kernel<<<grid, dim3(8, 32, 1)>>>();
    }
    // Inverse: out = x + gain * (OutF @ G)  (tf32, padded K)
    {
        dim3 grid(DD / GBN, NTOK / GBM, 1);
        gemm_tf32<<<grid, 256, GSMEM_BYTES>>>(NTOK, DD, KPAD, pO, KPAD,
                                              pG, DD, out, DD,
                                              1, x, gain);
    }
}